// round 1
// baseline (speedup 1.0000x reference)
#include <cuda_runtime.h>
#include <cuda_bf16.h>

// Shapes are fixed for this problem: F[8, 16384, 12] float32 -> out [8, 12, 16384] float32.
#define BATCH   8
#define SEQ_N   16384
#define NV      12
#define ROWS    (BATCH * SEQ_N)          // 131072 (b,n) rows
#define TOTAL   (ROWS * NV)              // 1572864 output elements
#define TPB_A   256
#define NBLK_A  (ROWS / TPB_A)           // 512
#define NEG_SLOPE 0.2f
#define BN_EPS  1e-5

// Scratch (device globals only; no allocation anywhere).
__device__ double2 g_partials[NBLK_A];
__device__ float2  g_coef;               // (scale, shift)

__device__ __forceinline__ float leaky1(float x) {
    // x>=0 -> x >= 0.2x ; x<0 -> 0.2x > x   => leaky == max(x, 0.2x)
    return fmaxf(x, NEG_SLOPE * x);
}

// ---------------------------------------------------------------------------
// Kernel A: per (b,n) row, compute Msum over the 12x12 pair-MLP, the 1x1 conv,
// write pre-BN y into d_out, and produce deterministic per-block sums of
// (y, y^2) in double precision.
// ---------------------------------------------------------------------------
__global__ __launch_bounds__(TPB_A)
void nlmp_main_kernel(const float* __restrict__ F,
                      const float* __restrict__ W1, const float* __restrict__ b1,
                      const float* __restrict__ W2, const float* __restrict__ b2,
                      const float* __restrict__ W3, const float* __restrict__ b3,
                      const float* __restrict__ cw, const float* __restrict__ cb,
                      float* __restrict__ y)
{
    const int t = blockIdx.x * TPB_A + threadIdx.x;   // row id, 0..ROWS-1

    // Broadcast weight loads (all threads hit the same lines).
    const float w100 = __ldg(W1 + 0), w101 = __ldg(W1 + 1);
    const float w110 = __ldg(W1 + 2), w111 = __ldg(W1 + 3);
    const float B10  = __ldg(b1 + 0), B11  = __ldg(b1 + 1);
    const float w200 = __ldg(W2 + 0), w201 = __ldg(W2 + 1);
    const float w210 = __ldg(W2 + 2), w211 = __ldg(W2 + 3);
    const float B20  = __ldg(b2 + 0), B21  = __ldg(b2 + 1);
    const float w30  = __ldg(W3 + 0), w31  = __ldg(W3 + 1);
    const float B3   = __ldg(b3 + 0);
    const float cw0  = __ldg(cw + 0), cw1  = __ldg(cw + 1);
    const float cb0  = __ldg(cb + 0);

    // Load the 12 features of this row (3x LDG.128, 16B-aligned: t*48 bytes).
    const float4* fv = reinterpret_cast<const float4*>(F) + (size_t)t * 3;
    const float4 f0 = fv[0], f1 = fv[1], f2 = fv[2];
    const float xs[NV] = { f0.x, f0.y, f0.z, f0.w,
                           f1.x, f1.y, f1.z, f1.w,
                           f2.x, f2.y, f2.z, f2.w };

    // Layer-1 separable precompute: a_h(i,j) = p_h[j] + q_h(i)
    //   p_h[j] = W1[h,0]*F[j] + b1[h]   (channel 0 of M is F[j])
    //   q_h(i) = W1[h,1]*F[i]           (channel 1 of M is F[i])
    float p0[NV], p1[NV];
    #pragma unroll
    for (int j = 0; j < NV; j++) {
        p0[j] = fmaf(w100, xs[j], B10);
        p1[j] = fmaf(w110, xs[j], B11);
    }

    const int b = t >> 14;                 // t / SEQ_N
    const int n = t & (SEQ_N - 1);
    float* outp = y + ((size_t)b * NV << 14) + n;   // out[b, i, n], stride SEQ_N over i
    const float* frow = F + (size_t)t * NV;

    float s1 = 0.f, s2 = 0.f;

    #pragma unroll 2
    for (int i = 0; i < NV; i++) {
        const float xi = __ldg(frow + i);           // L1 hit (line already resident)
        const float q0 = w101 * xi;
        const float q1 = w111 * xi;
        float accA = 0.f, accB = 0.f;               // split accumulators for ILP
        #pragma unroll
        for (int j = 0; j < NV; j++) {
            float a0 = p0[j] + q0;
            float a1 = p1[j] + q1;
            a0 = leaky1(a0);
            a1 = leaky1(a1);
            float g0 = fmaf(w200, a0, fmaf(w201, a1, B20));
            float g1 = fmaf(w210, a0, fmaf(w211, a1, B21));
            g0 = leaky1(g0);
            g1 = leaky1(g1);
            float o = fmaf(w30, g0, fmaf(w31, g1, B3));
            o = leaky1(o);
            if (j & 1) accB += o; else accA += o;
        }
        const float Ms = accA + accB;               // Msum[b,n,i]
        const float yv = fmaf(cw0, xi, fmaf(cw1, Ms, cb0));
        outp[(size_t)i << 14] = yv;                 // coalesced across the warp
        s1 += yv;
        s2 = fmaf(yv, yv, s2);
    }

    // Deterministic block reduction (double) -> one partial per block.
    double d1 = (double)s1, d2 = (double)s2;
    #pragma unroll
    for (int o = 16; o > 0; o >>= 1) {
        d1 += __shfl_down_sync(0xffffffffu, d1, o);
        d2 += __shfl_down_sync(0xffffffffu, d2, o);
    }
    __shared__ double sh1[TPB_A / 32], sh2[TPB_A / 32];
    const int lane = threadIdx.x & 31, warp = threadIdx.x >> 5;
    if (lane == 0) { sh1[warp] = d1; sh2[warp] = d2; }
    __syncthreads();
    if (threadIdx.x == 0) {
        double t1 = 0.0, t2 = 0.0;
        #pragma unroll
        for (int w = 0; w < TPB_A / 32; w++) { t1 += sh1[w]; t2 += sh2[w]; }
        g_partials[blockIdx.x] = make_double2(t1, t2);
    }
}

// ---------------------------------------------------------------------------
// Kernel B: reduce 512 partials -> BN affine coefficients (scale, shift).
// ---------------------------------------------------------------------------
__global__ __launch_bounds__(512)
void nlmp_stats_kernel(const float* __restrict__ gamma, const float* __restrict__ beta)
{
    const int tid = threadIdx.x;           // 512 threads, one per partial
    double2 v = g_partials[tid];
    double d1 = v.x, d2 = v.y;
    #pragma unroll
    for (int o = 16; o > 0; o >>= 1) {
        d1 += __shfl_down_sync(0xffffffffu, d1, o);
        d2 += __shfl_down_sync(0xffffffffu, d2, o);
    }
    __shared__ double sh1[16], sh2[16];
    const int lane = tid & 31, warp = tid >> 5;
    if (lane == 0) { sh1[warp] = d1; sh2[warp] = d2; }
    __syncthreads();
    if (tid < 32) {
        d1 = (tid < 16) ? sh1[tid] : 0.0;
        d2 = (tid < 16) ? sh2[tid] : 0.0;
        #pragma unroll
        for (int o = 8; o > 0; o >>= 1) {
            d1 += __shfl_down_sync(0xffffffffu, d1, o);
            d2 += __shfl_down_sync(0xffffffffu, d2, o);
        }
        if (tid == 0) {
            const double M = (double)TOTAL;
            const double mean = d1 / M;
            const double var  = d2 / M - mean * mean;     // biased variance
            const double rs   = 1.0 / sqrt(var + BN_EPS);
            const float scale = (float)((double)__ldg(gamma) * rs);
            const float shift = (float)((double)__ldg(beta) - mean * (double)__ldg(gamma) * rs);
            g_coef = make_float2(scale, shift);
        }
    }
}

// ---------------------------------------------------------------------------
// Kernel C: in-place normalize + leaky over d_out (mostly L2 hits).
// ---------------------------------------------------------------------------
__global__ __launch_bounds__(256)
void nlmp_norm_kernel(float* __restrict__ y)
{
    const float2 c = g_coef;               // uniform broadcast load
    const int idx = blockIdx.x * 256 + threadIdx.x;   // TOTAL/4 float4s
    float4* p = reinterpret_cast<float4*>(y);
    float4 v = p[idx];
    v.x = leaky1(fmaf(v.x, c.x, c.y));
    v.y = leaky1(fmaf(v.y, c.x, c.y));
    v.z = leaky1(fmaf(v.z, c.x, c.y));
    v.w = leaky1(fmaf(v.w, c.x, c.y));
    p[idx] = v;
}

// ---------------------------------------------------------------------------
extern "C" void kernel_launch(void* const* d_in, const int* in_sizes, int n_in,
                              void* d_out, int out_size)
{
    const float* F    = (const float*)d_in[0];
    const float* W1   = (const float*)d_in[1];
    const float* b1   = (const float*)d_in[2];
    const float* W2   = (const float*)d_in[3];
    const float* b2   = (const float*)d_in[4];
    const float* W3   = (const float*)d_in[5];
    const float* b3   = (const float*)d_in[6];
    const float* cw   = (const float*)d_in[7];
    const float* cb   = (const float*)d_in[8];
    const float* gmma = (const float*)d_in[9];
    const float* beta = (const float*)d_in[10];
    float* out = (float*)d_out;

    nlmp_main_kernel<<<NBLK_A, TPB_A>>>(F, W1, b1, W2, b2, W3, b3, cw, cb, out);
    nlmp_stats_kernel<<<1, 512>>>(gmma, beta);
    nlmp_norm_kernel<<<(TOTAL / 4) / 256, 256>>>(out);
}